// round 6
// baseline (speedup 1.0000x reference)
#include <cuda_runtime.h>
#include <cuda_fp16.h>

typedef unsigned long long u64;

#define Nn   200000
#define Ee   3200000
#define Bb   512
#define EMB  32
#define HID  64
#define TPB  256
#define TILE 1024
#define NT   ((Nn + TILE - 1) / TILE)   // 196 scan tiles

// ---------------- scratch (device globals; no allocation) ----------------
__device__ uint4 g_h0h [Nn * 4];          // 12.8 MB fp16 h0   (32 ch)
__device__ uint4 g_ag1h[Nn * 4];          // 12.8 MB fp16 agg1
__device__ uint4 g_h1h [Nn * 8];          // 25.6 MB fp16 h1   (64 ch)
__device__ uint4 g_ag2h[Nn * 8];          // 25.6 MB fp16 agg2
__device__ int   g_csr [Ee];              // 12.8 MB
__device__ int   g_rowptr[Nn];
__device__ int   g_cursor[Nn];
__device__ int   g_deg [Nn];
__device__ float g_dinv[Nn];
__device__ float g_hg  [Bb * HID];
__device__ float g_cnt [Bb];
__device__ volatile unsigned g_tilest[NT];
__device__ u64   g_bar;                   // monotonic barrier counter (zero-init once)

// ---------------- helpers ----------------
__device__ __forceinline__ void red4(float4* p, float4 v) {
    asm volatile("red.global.add.v4.f32 [%0], {%1,%2,%3,%4};"
                 :: "l"(p), "f"(v.x), "f"(v.y), "f"(v.z), "f"(v.w) : "memory");
}
__device__ __forceinline__ u64 pack2(float x, float y) {
    u64 r; asm("mov.b64 %0, {%1, %2};" : "=l"(r) : "f"(x), "f"(y)); return r;
}
__device__ __forceinline__ void fma2(u64& d, u64 a, u64 b) {
    asm("fma.rn.f32x2 %0, %1, %2, %0;" : "+l"(d) : "l"(a), "l"(b));
}
__device__ __forceinline__ void unpack2(float& x, float& y, u64 v) {
    asm("mov.b64 {%0, %1}, %2;" : "=f"(x), "=f"(y) : "l"(v));
}
__device__ __forceinline__ unsigned ph2(float a, float b) {
    __half2 h = __floats2half2_rn(a, b); return *(unsigned*)&h;
}
#define UNPACK8(q, f) { \
    float2 _a = __half22float2(*(__half2*)&(q).x); \
    float2 _b = __half22float2(*(__half2*)&(q).y); \
    float2 _c = __half22float2(*(__half2*)&(q).z); \
    float2 _d = __half22float2(*(__half2*)&(q).w); \
    f[0]=_a.x; f[1]=_a.y; f[2]=_b.x; f[3]=_b.y; \
    f[4]=_c.x; f[5]=_c.y; f[6]=_d.x; f[7]=_d.y; }
#define ACCQ(q) { \
    float2 f0 = __half22float2(*(__half2*)&(q).x); \
    float2 f1 = __half22float2(*(__half2*)&(q).y); \
    float2 f2 = __half22float2(*(__half2*)&(q).z); \
    float2 f3 = __half22float2(*(__half2*)&(q).w); \
    a0+=f0.x; a1+=f0.y; a2+=f1.x; a3+=f1.y; \
    a4+=f2.x; a5+=f2.y; a6+=f3.x; a7+=f3.y; }

// software grid barrier: monotonic counter, no reset needed across replays.
// Safe because grid size == guaranteed-resident block count (occupancy API).
__device__ __forceinline__ void gbar() {
    __syncthreads();
    if (threadIdx.x == 0) {
        __threadfence();
        u64 old = atomicAdd(&g_bar, 1ULL);
        u64 target = (old / gridDim.x + 1ULL) * (u64)gridDim.x;
        while (*((volatile u64*)&g_bar) < target) { __nanosleep(128); }
        __threadfence();
    }
    __syncthreads();
}

// ---------------- the whole pipeline in one persistent kernel ----------------
__global__ void __launch_bounds__(TPB, 3)
k_all(const int* __restrict__ node_ids, const int* __restrict__ src,
      const int* __restrict__ dst, const int* __restrict__ graph_ids,
      const float4* __restrict__ emb,
      const float* __restrict__ Wse1, const float* __restrict__ Wne1, const float* __restrict__ b1,
      const float* __restrict__ Wse2, const float* __restrict__ Wne2, const float* __restrict__ b2,
      const float* __restrict__ Ps1,  const float* __restrict__ pb1,
      const float* __restrict__ Ps2,  const float* __restrict__ pb2,
      float* __restrict__ out)
{
    __shared__ float sW[2 * HID * HID];   // 32 KB, reused per phase
    __shared__ float sb[HID];
    __shared__ int   s_run;

    const int tid  = threadIdx.x;
    const int gtid = blockIdx.x * TPB + tid;
    const int gstr = gridDim.x * TPB;

    // ---- P0: zero ----
    for (int j = gtid; j < Nn;       j += gstr) g_deg[j] = 0;
    for (int j = gtid; j < Bb * HID; j += gstr) g_hg[j]  = 0.f;
    for (int j = gtid; j < Bb;       j += gstr) g_cnt[j] = 0.f;
    for (int j = gtid; j < NT;       j += gstr) g_tilest[j] = 0u;
    gbar();

    // ---- P1: degree hist + graph-count hist + embedding gather (fp16) ----
    for (int i = gtid; i < Ee; i += gstr) atomicAdd(&g_deg[dst[i]], 1);
    for (int i = gtid; i < Nn; i += gstr) atomicAdd(&g_cnt[graph_ids[i]], 1.0f);
    for (int i = gtid; i < Nn * 4; i += gstr) {
        int n = i >> 2, c = i & 3;
        float4 v0 = emb[node_ids[n] * 8 + c * 2 + 0];
        float4 v1 = emb[node_ids[n] * 8 + c * 2 + 1];
        uint4 o;
        o.x = ph2(v0.x, v0.y); o.y = ph2(v0.z, v0.w);
        o.z = ph2(v1.x, v1.y); o.w = ph2(v1.z, v1.w);
        g_h0h[n * 4 + c] = o;
    }
    gbar();

    // ---- P2: decoupled-lookback exclusive scan of deg -> rowptr/cursor, dinv ----
    for (int t = blockIdx.x; t < NT; t += gridDim.x) {
        int* ssum = (int*)sW;
        int base = t * TILE + tid * 4;
        int d[4]; int s = 0;
        #pragma unroll
        for (int it = 0; it < 4; it++) {
            int idx = base + it;
            d[it] = (idx < Nn) ? g_deg[idx] : 0;
            s += d[it];
        }
        ssum[tid] = s; __syncthreads();
        #pragma unroll
        for (int off = 1; off < 256; off <<= 1) {
            int x = (tid >= off) ? ssum[tid - off] : 0;
            __syncthreads();
            ssum[tid] += x;
            __syncthreads();
        }
        int texcl = ssum[tid] - s;
        int total = ssum[255];
        if (tid == 0) {
            if (t == 0) {
                g_tilest[0] = (2u << 30) | (unsigned)total;
                s_run = 0;
            } else {
                g_tilest[t] = (1u << 30) | (unsigned)total;
                int run = 0, p = t - 1;
                while (true) {
                    unsigned w = g_tilest[p];
                    unsigned f = w >> 30;
                    if (f == 2u) { run += (int)(w & 0x3FFFFFFFu); break; }
                    if (f == 1u) { run += (int)(w & 0x3FFFFFFFu); p--; }
                }
                g_tilest[t] = (2u << 30) | (unsigned)(run + total);
                s_run = run;
            }
        }
        __syncthreads();
        int ex = s_run + texcl;
        #pragma unroll
        for (int it = 0; it < 4; it++) {
            int idx = base + it;
            if (idx < Nn) {
                g_rowptr[idx] = ex;
                g_cursor[idx] = ex;
                int dd = d[it];
                g_dinv[idx] = (dd > 0) ? 1.0f / (float)dd : 0.0f;
                ex += dd;
            }
        }
        __syncthreads();
    }
    gbar();

    // ---- P3: CSR fill ----
    for (int e = gtid; e < Ee; e += gstr) {
        int p = atomicAdd(&g_cursor[dst[e]], 1);
        g_csr[p] = src[e];
    }
    gbar();

    // ---- P4: agg1 (4 threads/node x 8 ch), fp16 read, fp32 acc ----
    for (int t = gtid; t < Nn * 4; t += gstr) {
        int n = t >> 2, c = t & 3;
        int beg = g_rowptr[n], cnt = g_deg[n];
        float a0=0.f,a1=0.f,a2=0.f,a3=0.f,a4=0.f,a5=0.f,a6=0.f,a7=0.f;
        int i = 0;
        for (; i + 3 < cnt; i += 4) {
            int s0 = __ldg(&g_csr[beg+i+0]);
            int s1 = __ldg(&g_csr[beg+i+1]);
            int s2 = __ldg(&g_csr[beg+i+2]);
            int s3 = __ldg(&g_csr[beg+i+3]);
            uint4 q0 = g_h0h[s0*4+c], q1 = g_h0h[s1*4+c];
            uint4 q2 = g_h0h[s2*4+c], q3 = g_h0h[s3*4+c];
            ACCQ(q0) ACCQ(q1) ACCQ(q2) ACCQ(q3)
        }
        for (; i < cnt; i++) {
            int s = __ldg(&g_csr[beg+i]);
            uint4 q = g_h0h[s*4+c];
            ACCQ(q)
        }
        float dinv = g_dinv[n];
        uint4 o;
        o.x = ph2(a0*dinv, a1*dinv); o.y = ph2(a2*dinv, a3*dinv);
        o.z = ph2(a4*dinv, a5*dinv); o.w = ph2(a6*dinv, a7*dinv);
        g_ag1h[n*4 + c] = o;
    }
    gbar();

    // ---- P5: update1 (half-split outputs, FFMA2, weights in smem) ----
    for (int i = tid; i < EMB * HID; i += TPB) { sW[i] = Wse1[i]; sW[EMB*HID + i] = Wne1[i]; }
    if (tid < HID) sb[tid] = b1[tid];
    __syncthreads();
    for (int n = gtid; n < Nn; n += gstr) {
        #pragma unroll 1
        for (int h = 0; h < 2; h++) {
            u64 acc[16];
            #pragma unroll
            for (int j2 = 0; j2 < 16; j2++) acc[j2] = pack2(sb[h*32 + 2*j2], sb[h*32 + 2*j2+1]);
            #pragma unroll 1
            for (int kk = 0; kk < 4; kk++) {
                uint4 hq = g_h0h[n*4 + kk];
                uint4 aq = g_ag1h[n*4 + kk];
                float hf[8], af[8];
                UNPACK8(hq, hf) UNPACK8(aq, af)
                #pragma unroll
                for (int ch = 0; ch < 8; ch++) {
                    int k = kk*8 + ch;
                    const u64* ws = (const u64*)&sW[k * HID + h*32];
                    const u64* wn = (const u64*)&sW[(EMB + k) * HID + h*32];
                    u64 bh = pack2(hf[ch], hf[ch]);
                    u64 ba = pack2(af[ch], af[ch]);
                    #pragma unroll
                    for (int j2 = 0; j2 < 16; j2++) {
                        fma2(acc[j2], bh, ws[j2]);
                        fma2(acc[j2], ba, wn[j2]);
                    }
                }
            }
            #pragma unroll
            for (int j8 = 0; j8 < 4; j8++) {
                float x0,x1,x2,x3,x4,x5,x6,x7;
                unpack2(x0,x1, acc[j8*4+0]); unpack2(x2,x3, acc[j8*4+1]);
                unpack2(x4,x5, acc[j8*4+2]); unpack2(x6,x7, acc[j8*4+3]);
                uint4 o;
                o.x = ph2(fmaxf(x0,0.f), fmaxf(x1,0.f));
                o.y = ph2(fmaxf(x2,0.f), fmaxf(x3,0.f));
                o.z = ph2(fmaxf(x4,0.f), fmaxf(x5,0.f));
                o.w = ph2(fmaxf(x6,0.f), fmaxf(x7,0.f));
                g_h1h[n*8 + h*4 + j8] = o;
            }
        }
    }
    gbar();

    // ---- P6: agg2 (8 threads/node x 8 ch) ----
    for (int t = gtid; t < Nn * 8; t += gstr) {
        int n = t >> 3, c = t & 7;
        int beg = g_rowptr[n], cnt = g_deg[n];
        float a0=0.f,a1=0.f,a2=0.f,a3=0.f,a4=0.f,a5=0.f,a6=0.f,a7=0.f;
        int i = 0;
        for (; i + 3 < cnt; i += 4) {
            int s0 = __ldg(&g_csr[beg+i+0]);
            int s1 = __ldg(&g_csr[beg+i+1]);
            int s2 = __ldg(&g_csr[beg+i+2]);
            int s3 = __ldg(&g_csr[beg+i+3]);
            uint4 q0 = g_h1h[s0*8+c], q1 = g_h1h[s1*8+c];
            uint4 q2 = g_h1h[s2*8+c], q3 = g_h1h[s3*8+c];
            ACCQ(q0) ACCQ(q1) ACCQ(q2) ACCQ(q3)
        }
        for (; i < cnt; i++) {
            int s = __ldg(&g_csr[beg+i]);
            uint4 q = g_h1h[s*8+c];
            ACCQ(q)
        }
        float dinv = g_dinv[n];
        uint4 o;
        o.x = ph2(a0*dinv, a1*dinv); o.y = ph2(a2*dinv, a3*dinv);
        o.z = ph2(a4*dinv, a5*dinv); o.w = ph2(a6*dinv, a7*dinv);
        g_ag2h[n*8 + c] = o;
    }
    gbar();

    // ---- P7: update2 (half-split) + per-graph pooling ----
    __syncthreads();
    for (int i = tid; i < HID * HID; i += TPB) { sW[i] = Wse2[i]; sW[HID*HID + i] = Wne2[i]; }
    if (tid < HID) sb[tid] = b2[tid];
    __syncthreads();
    for (int n = gtid; n < Nn; n += gstr) {
        int g = graph_ids[n];
        float4* hgv = (float4*)&g_hg[g * HID];
        #pragma unroll 1
        for (int h = 0; h < 2; h++) {
            u64 acc[16];
            #pragma unroll
            for (int j2 = 0; j2 < 16; j2++) acc[j2] = pack2(sb[h*32 + 2*j2], sb[h*32 + 2*j2+1]);
            #pragma unroll 1
            for (int kk = 0; kk < 8; kk++) {
                uint4 hq = g_h1h[n*8 + kk];
                uint4 aq = g_ag2h[n*8 + kk];
                float hf[8], af[8];
                UNPACK8(hq, hf) UNPACK8(aq, af)
                #pragma unroll
                for (int ch = 0; ch < 8; ch++) {
                    int k = kk*8 + ch;
                    const u64* ws = (const u64*)&sW[k * HID + h*32];
                    const u64* wn = (const u64*)&sW[(HID + k) * HID + h*32];
                    u64 bh = pack2(hf[ch], hf[ch]);
                    u64 ba = pack2(af[ch], af[ch]);
                    #pragma unroll
                    for (int j2 = 0; j2 < 16; j2++) {
                        fma2(acc[j2], bh, ws[j2]);
                        fma2(acc[j2], ba, wn[j2]);
                    }
                }
            }
            #pragma unroll
            for (int j4 = 0; j4 < 8; j4++) {
                float x0,x1,x2,x3;
                unpack2(x0, x1, acc[j4*2+0]);
                unpack2(x2, x3, acc[j4*2+1]);
                float4 o = make_float4(fmaxf(x0,0.f), fmaxf(x1,0.f), fmaxf(x2,0.f), fmaxf(x3,0.f));
                red4(&hgv[h*8 + j4], o);
            }
        }
    }
    gbar();

    // ---- P8: scorer MLP over 512 graphs ----
    if (blockIdx.x < (Bb + TPB - 1) / TPB) {
        for (int i = tid; i < HID * HID; i += TPB) sW[i] = Ps1[i];
        __syncthreads();
        int g = blockIdx.x * TPB + tid;
        if (g < Bb) {
            float inv = 1.0f / fmaxf(g_cnt[g], 1.0f);
            float hv[HID];
            #pragma unroll
            for (int k = 0; k < HID; k++) hv[k] = g_hg[g * HID + k] * inv;
            float s = pb2[0];
            #pragma unroll 1
            for (int j = 0; j < HID; j++) {
                float t = pb1[j];
                #pragma unroll
                for (int k = 0; k < HID; k++) t += hv[k] * sW[k * HID + j];
                s += fmaxf(t, 0.f) * Ps2[j];
            }
            out[g] = s;
        }
    }
}

// ---------------- launcher ----------------
extern "C" void kernel_launch(void* const* d_in, const int* in_sizes, int n_in,
                              void* d_out, int out_size) {
    const int*    node_ids  = (const int*)   d_in[0];
    const int*    src       = (const int*)   d_in[1];
    const int*    dst       = (const int*)   d_in[2];
    const int*    graph_ids = (const int*)   d_in[3];
    const float4* emb       = (const float4*)d_in[4];
    const float*  W_self1   = (const float*) d_in[5];
    const float*  W_neigh1  = (const float*) d_in[6];
    const float*  b1        = (const float*) d_in[7];
    const float*  W_self2   = (const float*) d_in[8];
    const float*  W_neigh2  = (const float*) d_in[9];
    const float*  b2        = (const float*) d_in[10];
    const float*  Ws1       = (const float*) d_in[11];
    const float*  bs1       = (const float*) d_in[12];
    const float*  Ws2       = (const float*) d_in[13];
    const float*  bs2       = (const float*) d_in[14];
    float* out = (float*)d_out;

    int dev = 0;
    cudaGetDevice(&dev);
    int sms = 0;
    cudaDeviceGetAttribute(&sms, cudaDevAttrMultiProcessorCount, dev);
    int maxb = 0;
    cudaOccupancyMaxActiveBlocksPerMultiprocessor(&maxb, k_all, TPB, 0);
    if (maxb < 1) maxb = 1;
    int grid = sms * maxb;

    k_all<<<grid, TPB>>>(node_ids, src, dst, graph_ids, emb,
                         W_self1, W_neigh1, b1,
                         W_self2, W_neigh2, b2,
                         Ws1, bs1, Ws2, bs2, out);
}

// round 7
// speedup vs baseline: 1.1592x; 1.1592x over previous
#include <cuda_runtime.h>
#include <cuda_fp16.h>

typedef unsigned long long u64;

#define Nn   200000
#define Ee   3200000
#define Bb   512
#define EMB  32
#define HID  64
#define TILE 1024
#define NT   ((Nn + TILE - 1) / TILE)   // 196 scan tiles

// ---------------- scratch (device globals) ----------------
__device__ uint4 g_h0h [Nn * 4];          // 12.8 MB fp16 h0
__device__ uint4 g_ag1h[Nn * 4];          // 12.8 MB fp16 agg1
__device__ uint4 g_h1h [Nn * 8];          // 25.6 MB fp16 h1
__device__ uint4 g_ag2h[Nn * 8];          // 25.6 MB fp16 agg2
__device__ int   g_csr [Ee];              // 12.8 MB
__device__ int   g_rowptr[Nn];
__device__ int   g_cursor[Nn];
__device__ int   g_deg [Nn];
__device__ float g_dinv[Nn];
__device__ float g_hg  [Bb * HID];
__device__ float g_cnt [Bb];
__device__ volatile unsigned g_tilest[NT];
__device__ int   g_ticket;

// ---------------- helpers ----------------
__device__ __forceinline__ void red4(float4* p, float4 v) {
    asm volatile("red.global.add.v4.f32 [%0], {%1,%2,%3,%4};"
                 :: "l"(p), "f"(v.x), "f"(v.y), "f"(v.z), "f"(v.w) : "memory");
}
__device__ __forceinline__ u64 pack2(float x, float y) {
    u64 r; asm("mov.b64 %0, {%1, %2};" : "=l"(r) : "f"(x), "f"(y)); return r;
}
__device__ __forceinline__ void fma2(u64& d, u64 a, u64 b) {
    asm("fma.rn.f32x2 %0, %1, %2, %0;" : "+l"(d) : "l"(a), "l"(b));
}
__device__ __forceinline__ void unpack2(float& x, float& y, u64 v) {
    asm("mov.b64 {%0, %1}, %2;" : "=f"(x), "=f"(y) : "l"(v));
}
__device__ __forceinline__ unsigned ph2(float a, float b) {
    __half2 h = __floats2half2_rn(a, b); return *(unsigned*)&h;
}
__device__ __forceinline__ float hget(const uint4& q, int ch) {
    unsigned w = (ch < 2) ? q.x : (ch < 4) ? q.y : (ch < 6) ? q.z : q.w;
    __half2 h = *(__half2*)&w;
    return (ch & 1) ? __high2float(h) : __low2float(h);
}
#define ACCQ(q) { \
    float2 f0 = __half22float2(*(__half2*)&(q).x); \
    float2 f1 = __half22float2(*(__half2*)&(q).y); \
    float2 f2 = __half22float2(*(__half2*)&(q).z); \
    float2 f3 = __half22float2(*(__half2*)&(q).w); \
    a0+=f0.x; a1+=f0.y; a2+=f1.x; a3+=f1.y; \
    a4+=f2.x; a5+=f2.y; a6+=f3.x; a7+=f3.y; }

// ---------------- setup kernels ----------------

__global__ void k_zero() {
    int i = blockIdx.x * blockDim.x + threadIdx.x;
    int stride = gridDim.x * blockDim.x;
    for (int j = i; j < Nn;       j += stride) g_deg[j] = 0;
    for (int j = i; j < Bb * HID; j += stride) g_hg[j]  = 0.f;
    for (int j = i; j < NT;       j += stride) g_tilest[j] = 0u;
    if (i < Bb) g_cnt[i] = 0.f;
    if (i == 0) g_ticket = 0;
}

__global__ void k_deg_gather(const int* __restrict__ dst,
                             const int* __restrict__ graph_ids,
                             const int* __restrict__ node_ids,
                             const float4* __restrict__ emb) {
    int i = blockIdx.x * blockDim.x + threadIdx.x;
    if (i < Ee) atomicAdd(&g_deg[dst[i]], 1);
    if (i < Nn) atomicAdd(&g_cnt[graph_ids[i]], 1.0f);
    if (i < Nn * 4) {
        int n = i >> 2, c = i & 3;
        float4 v0 = emb[node_ids[n] * 8 + c * 2 + 0];
        float4 v1 = emb[node_ids[n] * 8 + c * 2 + 1];
        uint4 o;
        o.x = ph2(v0.x, v0.y); o.y = ph2(v0.z, v0.w);
        o.z = ph2(v1.x, v1.y); o.w = ph2(v1.z, v1.w);
        g_h0h[n * 4 + c] = o;
    }
}

// single-pass decoupled-lookback exclusive scan
__global__ void __launch_bounds__(256) k_scan() {
    __shared__ int s_ticket, s_run;
    __shared__ int ssum[256];
    int tid = threadIdx.x;
    if (tid == 0) s_ticket = atomicAdd(&g_ticket, 1);
    __syncthreads();
    int t = s_ticket;
    int base = t * TILE + tid * 4;
    int d[4]; int s = 0;
    #pragma unroll
    for (int it = 0; it < 4; it++) {
        int idx = base + it;
        d[it] = (idx < Nn) ? g_deg[idx] : 0;
        s += d[it];
    }
    ssum[tid] = s; __syncthreads();
    #pragma unroll
    for (int off = 1; off < 256; off <<= 1) {
        int x = (tid >= off) ? ssum[tid - off] : 0;
        __syncthreads();
        ssum[tid] += x;
        __syncthreads();
    }
    int texcl = ssum[tid] - s;
    int total = ssum[255];
    if (tid == 0) {
        if (t == 0) {
            g_tilest[0] = (2u << 30) | (unsigned)total;
            s_run = 0;
        } else {
            g_tilest[t] = (1u << 30) | (unsigned)total;
            int run = 0, p = t - 1;
            while (true) {
                unsigned w = g_tilest[p];
                unsigned f = w >> 30;
                if (f == 2u) { run += (int)(w & 0x3FFFFFFFu); break; }
                if (f == 1u) { run += (int)(w & 0x3FFFFFFFu); p--; }
            }
            g_tilest[t] = (2u << 30) | (unsigned)(run + total);
            s_run = run;
        }
    }
    __syncthreads();
    int ex = s_run + texcl;
    #pragma unroll
    for (int it = 0; it < 4; it++) {
        int idx = base + it;
        if (idx < Nn) {
            g_rowptr[idx] = ex;
            g_cursor[idx] = ex;
            int dd = d[it];
            g_dinv[idx] = (dd > 0) ? 1.0f / (float)dd : 0.0f;
            ex += dd;
        }
    }
}

__global__ void k_fill(const int* __restrict__ src, const int* __restrict__ dst) {
    int e = blockIdx.x * blockDim.x + threadIdx.x;
    if (e >= Ee) return;
    int p = atomicAdd(&g_cursor[dst[e]], 1);
    g_csr[p] = src[e];
}

// ---------------- aggregation: 8-deep MLP pipeline ----------------

__global__ void k_agg1() {
    int t = blockIdx.x * blockDim.x + threadIdx.x;
    if (t >= Nn * 4) return;
    int n = t >> 2, c = t & 3;
    int beg = g_rowptr[n], cnt = g_deg[n];
    float a0=0.f,a1=0.f,a2=0.f,a3=0.f,a4=0.f,a5=0.f,a6=0.f,a7=0.f;
    int i = 0;
    for (; i + 7 < cnt; i += 8) {
        int s0 = __ldg(&g_csr[beg+i+0]), s1 = __ldg(&g_csr[beg+i+1]);
        int s2 = __ldg(&g_csr[beg+i+2]), s3 = __ldg(&g_csr[beg+i+3]);
        int s4 = __ldg(&g_csr[beg+i+4]), s5 = __ldg(&g_csr[beg+i+5]);
        int s6 = __ldg(&g_csr[beg+i+6]), s7 = __ldg(&g_csr[beg+i+7]);
        uint4 q0 = g_h0h[s0*4+c], q1 = g_h0h[s1*4+c];
        uint4 q2 = g_h0h[s2*4+c], q3 = g_h0h[s3*4+c];
        uint4 q4 = g_h0h[s4*4+c], q5 = g_h0h[s5*4+c];
        uint4 q6 = g_h0h[s6*4+c], q7 = g_h0h[s7*4+c];
        ACCQ(q0) ACCQ(q1) ACCQ(q2) ACCQ(q3)
        ACCQ(q4) ACCQ(q5) ACCQ(q6) ACCQ(q7)
    }
    for (; i < cnt; i++) {
        int s = __ldg(&g_csr[beg+i]);
        uint4 q = g_h0h[s*4+c];
        ACCQ(q)
    }
    float dinv = g_dinv[n];
    uint4 o;
    o.x = ph2(a0*dinv, a1*dinv); o.y = ph2(a2*dinv, a3*dinv);
    o.z = ph2(a4*dinv, a5*dinv); o.w = ph2(a6*dinv, a7*dinv);
    g_ag1h[n*4 + c] = o;
}

__global__ void k_agg2() {
    int t = blockIdx.x * blockDim.x + threadIdx.x;
    if (t >= Nn * 8) return;
    int n = t >> 3, c = t & 7;
    int beg = g_rowptr[n], cnt = g_deg[n];
    float a0=0.f,a1=0.f,a2=0.f,a3=0.f,a4=0.f,a5=0.f,a6=0.f,a7=0.f;
    int i = 0;
    for (; i + 7 < cnt; i += 8) {
        int s0 = __ldg(&g_csr[beg+i+0]), s1 = __ldg(&g_csr[beg+i+1]);
        int s2 = __ldg(&g_csr[beg+i+2]), s3 = __ldg(&g_csr[beg+i+3]);
        int s4 = __ldg(&g_csr[beg+i+4]), s5 = __ldg(&g_csr[beg+i+5]);
        int s6 = __ldg(&g_csr[beg+i+6]), s7 = __ldg(&g_csr[beg+i+7]);
        uint4 q0 = g_h1h[s0*8+c], q1 = g_h1h[s1*8+c];
        uint4 q2 = g_h1h[s2*8+c], q3 = g_h1h[s3*8+c];
        uint4 q4 = g_h1h[s4*8+c], q5 = g_h1h[s5*8+c];
        uint4 q6 = g_h1h[s6*8+c], q7 = g_h1h[s7*8+c];
        ACCQ(q0) ACCQ(q1) ACCQ(q2) ACCQ(q3)
        ACCQ(q4) ACCQ(q5) ACCQ(q6) ACCQ(q7)
    }
    for (; i < cnt; i++) {
        int s = __ldg(&g_csr[beg+i]);
        uint4 q = g_h1h[s*8+c];
        ACCQ(q)
    }
    float dinv = g_dinv[n];
    uint4 o;
    o.x = ph2(a0*dinv, a1*dinv); o.y = ph2(a2*dinv, a3*dinv);
    o.z = ph2(a4*dinv, a5*dinv); o.w = ph2(a6*dinv, a7*dinv);
    g_ag2h[n*8 + c] = o;
}

// ---------------- dense updates: 2 nodes/thread, quarter-split, LDS.128 weights ------

__global__ void __launch_bounds__(256)
k_update1(const float* __restrict__ Wse, const float* __restrict__ Wne,
          const float* __restrict__ b) {
    __shared__ float sW[2 * EMB * HID];   // 16 KB
    __shared__ float sb[HID];
    int tid = threadIdx.x;
    for (int i = tid; i < EMB * HID; i += 256) { sW[i] = Wse[i]; sW[EMB*HID + i] = Wne[i]; }
    if (tid < HID) sb[tid] = b[tid];
    __syncthreads();

    int t = blockIdx.x * 256 + tid;
    if (t >= Nn / 2) return;          // Nn even: exactly 2 nodes per thread
    int n0 = t * 2, n1 = n0 + 1;

    #pragma unroll 1
    for (int q = 0; q < 4; q++) {     // quarter = 16 output cols
        u64 acc0[8], acc1[8];
        #pragma unroll
        for (int j2 = 0; j2 < 8; j2++) {
            u64 bi = pack2(sb[q*16 + 2*j2], sb[q*16 + 2*j2 + 1]);
            acc0[j2] = bi; acc1[j2] = bi;
        }
        #pragma unroll 1
        for (int kk = 0; kk < 4; kk++) {
            uint4 qh0 = g_h0h[n0*4 + kk], qa0 = g_ag1h[n0*4 + kk];
            uint4 qh1 = g_h0h[n1*4 + kk], qa1 = g_ag1h[n1*4 + kk];
            #pragma unroll
            for (int ch = 0; ch < 8; ch++) {
                int k = kk*8 + ch;
                const ulonglong2* ws = (const ulonglong2*)&sW[k * HID + q*16];
                const ulonglong2* wn = (const ulonglong2*)&sW[(EMB + k) * HID + q*16];
                float h0 = hget(qh0, ch), a0f = hget(qa0, ch);
                float h1 = hget(qh1, ch), a1f = hget(qa1, ch);
                u64 bh0 = pack2(h0, h0), ba0 = pack2(a0f, a0f);
                u64 bh1 = pack2(h1, h1), ba1 = pack2(a1f, a1f);
                #pragma unroll
                for (int j4 = 0; j4 < 4; j4++) {
                    ulonglong2 w = ws[j4], v = wn[j4];
                    fma2(acc0[j4*2+0], bh0, w.x); fma2(acc0[j4*2+1], bh0, w.y);
                    fma2(acc1[j4*2+0], bh1, w.x); fma2(acc1[j4*2+1], bh1, w.y);
                    fma2(acc0[j4*2+0], ba0, v.x); fma2(acc0[j4*2+1], ba0, v.y);
                    fma2(acc1[j4*2+0], ba1, v.x); fma2(acc1[j4*2+1], ba1, v.y);
                }
            }
        }
        // store quarter: 16 fp16 = 2 uint4 per node
        #pragma unroll
        for (int half = 0; half < 2; half++) {
            float x0,x1,x2,x3,x4,x5,x6,x7;
            unpack2(x0,x1, acc0[half*4+0]); unpack2(x2,x3, acc0[half*4+1]);
            unpack2(x4,x5, acc0[half*4+2]); unpack2(x6,x7, acc0[half*4+3]);
            uint4 o;
            o.x = ph2(fmaxf(x0,0.f), fmaxf(x1,0.f));
            o.y = ph2(fmaxf(x2,0.f), fmaxf(x3,0.f));
            o.z = ph2(fmaxf(x4,0.f), fmaxf(x5,0.f));
            o.w = ph2(fmaxf(x6,0.f), fmaxf(x7,0.f));
            g_h1h[n0*8 + q*2 + half] = o;
            unpack2(x0,x1, acc1[half*4+0]); unpack2(x2,x3, acc1[half*4+1]);
            unpack2(x4,x5, acc1[half*4+2]); unpack2(x6,x7, acc1[half*4+3]);
            o.x = ph2(fmaxf(x0,0.f), fmaxf(x1,0.f));
            o.y = ph2(fmaxf(x2,0.f), fmaxf(x3,0.f));
            o.z = ph2(fmaxf(x4,0.f), fmaxf(x5,0.f));
            o.w = ph2(fmaxf(x6,0.f), fmaxf(x7,0.f));
            g_h1h[n1*8 + q*2 + half] = o;
        }
    }
}

__global__ void __launch_bounds__(256)
k_update2(const float* __restrict__ Wse, const float* __restrict__ Wne,
          const float* __restrict__ b, const int* __restrict__ graph_ids) {
    __shared__ float sW[2 * HID * HID];   // 32 KB
    __shared__ float sb[HID];
    int tid = threadIdx.x;
    for (int i = tid; i < HID * HID; i += 256) { sW[i] = Wse[i]; sW[HID*HID + i] = Wne[i]; }
    if (tid < HID) sb[tid] = b[tid];
    __syncthreads();

    int t = blockIdx.x * 256 + tid;
    if (t >= Nn / 2) return;
    int n0 = t * 2, n1 = n0 + 1;
    int g0 = graph_ids[n0], g1 = graph_ids[n1];
    float4* hg0 = (float4*)&g_hg[g0 * HID];
    float4* hg1 = (float4*)&g_hg[g1 * HID];

    #pragma unroll 1
    for (int q = 0; q < 4; q++) {
        u64 acc0[8], acc1[8];
        #pragma unroll
        for (int j2 = 0; j2 < 8; j2++) {
            u64 bi = pack2(sb[q*16 + 2*j2], sb[q*16 + 2*j2 + 1]);
            acc0[j2] = bi; acc1[j2] = bi;
        }
        #pragma unroll 1
        for (int kk = 0; kk < 8; kk++) {
            uint4 qh0 = g_h1h[n0*8 + kk], qa0 = g_ag2h[n0*8 + kk];
            uint4 qh1 = g_h1h[n1*8 + kk], qa1 = g_ag2h[n1*8 + kk];
            #pragma unroll
            for (int ch = 0; ch < 8; ch++) {
                int k = kk*8 + ch;
                const ulonglong2* ws = (const ulonglong2*)&sW[k * HID + q*16];
                const ulonglong2* wn = (const ulonglong2*)&sW[(HID + k) * HID + q*16];
                float h0 = hget(qh0, ch), a0f = hget(qa0, ch);
                float h1 = hget(qh1, ch), a1f = hget(qa1, ch);
                u64 bh0 = pack2(h0, h0), ba0 = pack2(a0f, a0f);
                u64 bh1 = pack2(h1, h1), ba1 = pack2(a1f, a1f);
                #pragma unroll
                for (int j4 = 0; j4 < 4; j4++) {
                    ulonglong2 w = ws[j4], v = wn[j4];
                    fma2(acc0[j4*2+0], bh0, w.x); fma2(acc0[j4*2+1], bh0, w.y);
                    fma2(acc1[j4*2+0], bh1, w.x); fma2(acc1[j4*2+1], bh1, w.y);
                    fma2(acc0[j4*2+0], ba0, v.x); fma2(acc0[j4*2+1], ba0, v.y);
                    fma2(acc1[j4*2+0], ba1, v.x); fma2(acc1[j4*2+1], ba1, v.y);
                }
            }
        }
        // pool quarter: 16 floats = 4 float4 per node (red to hg)
        #pragma unroll
        for (int j4 = 0; j4 < 4; j4++) {
            float x0,x1,x2,x3;
            unpack2(x0, x1, acc0[j4*2+0]);
            unpack2(x2, x3, acc0[j4*2+1]);
            red4(&hg0[q*4 + j4], make_float4(fmaxf(x0,0.f), fmaxf(x1,0.f),
                                             fmaxf(x2,0.f), fmaxf(x3,0.f)));
            unpack2(x0, x1, acc1[j4*2+0]);
            unpack2(x2, x3, acc1[j4*2+1]);
            red4(&hg1[q*4 + j4], make_float4(fmaxf(x0,0.f), fmaxf(x1,0.f),
                                             fmaxf(x2,0.f), fmaxf(x3,0.f)));
        }
    }
}

// scorer
__global__ void k_final(const float* __restrict__ Ws1, const float* __restrict__ bs1,
                        const float* __restrict__ Ws2, const float* __restrict__ bs2,
                        float* __restrict__ out) {
    __shared__ float sW[HID * HID];
    int tid = threadIdx.x;
    for (int i = tid; i < HID * HID; i += 64) sW[i] = Ws1[i];
    __syncthreads();

    int g = blockIdx.x * 64 + tid;
    if (g >= Bb) return;

    float inv = 1.0f / fmaxf(g_cnt[g], 1.0f);
    float hv[HID];
    #pragma unroll
    for (int k = 0; k < HID; k++) hv[k] = g_hg[g * HID + k] * inv;

    float s = bs2[0];
    #pragma unroll 1
    for (int j = 0; j < HID; j++) {
        float t = bs1[j];
        #pragma unroll
        for (int k = 0; k < HID; k++) t += hv[k] * sW[k * HID + j];
        s += fmaxf(t, 0.f) * Ws2[j];
    }
    out[g] = s;
}

// ---------------- launcher ----------------
extern "C" void kernel_launch(void* const* d_in, const int* in_sizes, int n_in,
                              void* d_out, int out_size) {
    const int*    node_ids  = (const int*)   d_in[0];
    const int*    src       = (const int*)   d_in[1];
    const int*    dst       = (const int*)   d_in[2];
    const int*    graph_ids = (const int*)   d_in[3];
    const float4* emb       = (const float4*)d_in[4];
    const float*  W_self1   = (const float*) d_in[5];
    const float*  W_neigh1  = (const float*) d_in[6];
    const float*  b1        = (const float*) d_in[7];
    const float*  W_self2   = (const float*) d_in[8];
    const float*  W_neigh2  = (const float*) d_in[9];
    const float*  b2        = (const float*) d_in[10];
    const float*  Ws1       = (const float*) d_in[11];
    const float*  bs1       = (const float*) d_in[12];
    const float*  Ws2       = (const float*) d_in[13];
    const float*  bs2       = (const float*) d_in[14];
    float* out = (float*)d_out;

    k_zero      <<<512, 256>>>();
    k_deg_gather<<<(Ee + 255) / 256, 256>>>(dst, graph_ids, node_ids, emb);
    k_scan      <<<NT, 256>>>();
    k_fill      <<<(Ee + 255) / 256, 256>>>(src, dst);
    k_agg1      <<<(Nn * 4 + 255) / 256, 256>>>();
    k_update1   <<<(Nn/2 + 255) / 256, 256>>>(W_self1, W_neigh1, b1);
    k_agg2      <<<(Nn * 8 + 255) / 256, 256>>>();
    k_update2   <<<(Nn/2 + 255) / 256, 256>>>(W_self2, W_neigh2, b2, graph_ids);
    k_final     <<<(Bb + 63) / 64, 64>>>(Ws1, bs1, Ws2, bs2, out);
}

// round 8
// speedup vs baseline: 1.1654x; 1.0054x over previous
#include <cuda_runtime.h>
#include <cuda_fp16.h>

typedef unsigned long long u64;

#define Nn   200000
#define Ee   3200000
#define Bb   512
#define EMB  32
#define HID  64
#define TILE 1024
#define NT   ((Nn + TILE - 1) / TILE)   // 196 scan tiles

// ---------------- scratch (device globals) ----------------
__device__ uint4 g_h0h [Nn * 4];          // 12.8 MB fp16 h0
__device__ uint4 g_ag1h[Nn * 4];          // 12.8 MB fp16 agg1
__device__ uint4 g_h1h [Nn * 8];          // 25.6 MB fp16 h1
__device__ uint4 g_ag2h[Nn * 8];          // 25.6 MB fp16 agg2
__device__ int   g_csr [Ee];              // 12.8 MB
__device__ int   g_rank[Ee];              // 12.8 MB edge rank within dst
__device__ int   g_rowptr[Nn];
__device__ int   g_deg [Nn];
__device__ float g_dinv[Nn];
__device__ float g_hg  [Bb * HID];
__device__ float g_cnt [Bb];
__device__ volatile unsigned g_tilest[NT];
__device__ int   g_ticket;

// ---------------- helpers ----------------
__device__ __forceinline__ void red4(float4* p, float4 v) {
    asm volatile("red.global.add.v4.f32 [%0], {%1,%2,%3,%4};"
                 :: "l"(p), "f"(v.x), "f"(v.y), "f"(v.z), "f"(v.w) : "memory");
}
__device__ __forceinline__ u64 pack2(float x, float y) {
    u64 r; asm("mov.b64 %0, {%1, %2};" : "=l"(r) : "f"(x), "f"(y)); return r;
}
__device__ __forceinline__ void fma2(u64& d, u64 a, u64 b) {
    asm("fma.rn.f32x2 %0, %1, %2, %0;" : "+l"(d) : "l"(a), "l"(b));
}
__device__ __forceinline__ void unpack2(float& x, float& y, u64 v) {
    asm("mov.b64 {%0, %1}, %2;" : "=f"(x), "=f"(y) : "l"(v));
}
__device__ __forceinline__ unsigned ph2(float a, float b) {
    __half2 h = __floats2half2_rn(a, b); return *(unsigned*)&h;
}
__device__ __forceinline__ float hget(const uint4& q, int ch) {
    unsigned w = (ch < 2) ? q.x : (ch < 4) ? q.y : (ch < 6) ? q.z : q.w;
    __half2 h = *(__half2*)&w;
    return (ch & 1) ? __high2float(h) : __low2float(h);
}
// masked accumulate of a uint4 (8 fp16) with 0/1 weight m (FMA form)
#define ACCM(q, m) { \
    float2 f0 = __half22float2(*(__half2*)&(q).x); \
    float2 f1 = __half22float2(*(__half2*)&(q).y); \
    float2 f2 = __half22float2(*(__half2*)&(q).z); \
    float2 f3 = __half22float2(*(__half2*)&(q).w); \
    a0 = fmaf(m, f0.x, a0); a1 = fmaf(m, f0.y, a1); \
    a2 = fmaf(m, f1.x, a2); a3 = fmaf(m, f1.y, a3); \
    a4 = fmaf(m, f2.x, a4); a5 = fmaf(m, f2.y, a5); \
    a6 = fmaf(m, f3.x, a6); a7 = fmaf(m, f3.y, a7); }

// ---------------- setup kernels ----------------

__global__ void k_zero() {
    int i = blockIdx.x * blockDim.x + threadIdx.x;
    int stride = gridDim.x * blockDim.x;
    for (int j = i; j < Nn;       j += stride) g_deg[j] = 0;
    for (int j = i; j < Bb * HID; j += stride) g_hg[j]  = 0.f;
    for (int j = i; j < NT;       j += stride) g_tilest[j] = 0u;
    if (i < Bb) g_cnt[i] = 0.f;
    if (i == 0) g_ticket = 0;
}

// degree histogram (keep atomic return as edge rank) + graph-size histogram
__global__ void k_deg(const int* __restrict__ dst,
                      const int* __restrict__ graph_ids) {
    int i = blockIdx.x * blockDim.x + threadIdx.x;
    if (i < Ee) g_rank[i] = atomicAdd(&g_deg[dst[i]], 1);
    if (i < Nn) atomicAdd(&g_cnt[graph_ids[i]], 1.0f);
}

// single-pass decoupled-lookback exclusive scan
__global__ void __launch_bounds__(256) k_scan() {
    __shared__ int s_ticket, s_run;
    __shared__ int ssum[256];
    int tid = threadIdx.x;
    if (tid == 0) s_ticket = atomicAdd(&g_ticket, 1);
    __syncthreads();
    int t = s_ticket;
    int base = t * TILE + tid * 4;
    int d[4]; int s = 0;
    #pragma unroll
    for (int it = 0; it < 4; it++) {
        int idx = base + it;
        d[it] = (idx < Nn) ? g_deg[idx] : 0;
        s += d[it];
    }
    ssum[tid] = s; __syncthreads();
    #pragma unroll
    for (int off = 1; off < 256; off <<= 1) {
        int x = (tid >= off) ? ssum[tid - off] : 0;
        __syncthreads();
        ssum[tid] += x;
        __syncthreads();
    }
    int texcl = ssum[tid] - s;
    int total = ssum[255];
    if (tid == 0) {
        if (t == 0) {
            g_tilest[0] = (2u << 30) | (unsigned)total;
            s_run = 0;
        } else {
            g_tilest[t] = (1u << 30) | (unsigned)total;
            int run = 0, p = t - 1;
            while (true) {
                unsigned w = g_tilest[p];
                unsigned f = w >> 30;
                if (f == 2u) { run += (int)(w & 0x3FFFFFFFu); break; }
                if (f == 1u) { run += (int)(w & 0x3FFFFFFFu); p--; }
            }
            g_tilest[t] = (2u << 30) | (unsigned)(run + total);
            s_run = run;
        }
    }
    __syncthreads();
    int ex = s_run + texcl;
    #pragma unroll
    for (int it = 0; it < 4; it++) {
        int idx = base + it;
        if (idx < Nn) {
            g_rowptr[idx] = ex;
            int dd = d[it];
            g_dinv[idx] = (dd > 0) ? 1.0f / (float)dd : 0.0f;
            ex += dd;
        }
    }
}

// CSR fill (atomic-free: rank precomputed) + embedding gather fused in (idle-issue ride-along)
__global__ void k_fill_gather(const int* __restrict__ src, const int* __restrict__ dst,
                              const int* __restrict__ node_ids,
                              const float4* __restrict__ emb) {
    int i = blockIdx.x * blockDim.x + threadIdx.x;
    if (i < Ee) {
        int d = dst[i];
        g_csr[g_rowptr[d] + g_rank[i]] = src[i];
    }
    if (i < Nn * 4) {
        int n = i >> 2, c = i & 3;
        float4 v0 = emb[node_ids[n] * 8 + c * 2 + 0];
        float4 v1 = emb[node_ids[n] * 8 + c * 2 + 1];
        uint4 o;
        o.x = ph2(v0.x, v0.y); o.y = ph2(v0.z, v0.w);
        o.z = ph2(v1.x, v1.y); o.w = ph2(v1.z, v1.w);
        g_h0h[n * 4 + c] = o;
    }
}

// ---------------- aggregation: masked fixed-batch (MLP=8 incl. tails) ----------------

__global__ void k_agg1() {
    int t = blockIdx.x * blockDim.x + threadIdx.x;
    if (t >= Nn * 4) return;
    int n = t >> 2, c = t & 3;
    int beg = g_rowptr[n], cnt = g_deg[n];
    float a0=0.f,a1=0.f,a2=0.f,a3=0.f,a4=0.f,a5=0.f,a6=0.f,a7=0.f;
    for (int i = 0; i < cnt; i += 8) {
        int  idx[8];
        float m[8];
        #pragma unroll
        for (int j = 0; j < 8; j++) {
            int ii = i + j;
            int id = (ii < cnt) ? ii : cnt - 1;
            idx[j] = __ldg(&g_csr[beg + id]);
            m[j]   = (ii < cnt) ? 1.0f : 0.0f;
        }
        uint4 q0 = g_h0h[idx[0]*4+c], q1 = g_h0h[idx[1]*4+c];
        uint4 q2 = g_h0h[idx[2]*4+c], q3 = g_h0h[idx[3]*4+c];
        uint4 q4 = g_h0h[idx[4]*4+c], q5 = g_h0h[idx[5]*4+c];
        uint4 q6 = g_h0h[idx[6]*4+c], q7 = g_h0h[idx[7]*4+c];
        ACCM(q0, m[0]) ACCM(q1, m[1]) ACCM(q2, m[2]) ACCM(q3, m[3])
        ACCM(q4, m[4]) ACCM(q5, m[5]) ACCM(q6, m[6]) ACCM(q7, m[7])
    }
    float dinv = g_dinv[n];
    uint4 o;
    o.x = ph2(a0*dinv, a1*dinv); o.y = ph2(a2*dinv, a3*dinv);
    o.z = ph2(a4*dinv, a5*dinv); o.w = ph2(a6*dinv, a7*dinv);
    g_ag1h[n*4 + c] = o;
}

__global__ void k_agg2() {
    int t = blockIdx.x * blockDim.x + threadIdx.x;
    if (t >= Nn * 8) return;
    int n = t >> 3, c = t & 7;
    int beg = g_rowptr[n], cnt = g_deg[n];
    float a0=0.f,a1=0.f,a2=0.f,a3=0.f,a4=0.f,a5=0.f,a6=0.f,a7=0.f;
    for (int i = 0; i < cnt; i += 8) {
        int  idx[8];
        float m[8];
        #pragma unroll
        for (int j = 0; j < 8; j++) {
            int ii = i + j;
            int id = (ii < cnt) ? ii : cnt - 1;
            idx[j] = __ldg(&g_csr[beg + id]);
            m[j]   = (ii < cnt) ? 1.0f : 0.0f;
        }
        uint4 q0 = g_h1h[idx[0]*8+c], q1 = g_h1h[idx[1]*8+c];
        uint4 q2 = g_h1h[idx[2]*8+c], q3 = g_h1h[idx[3]*8+c];
        uint4 q4 = g_h1h[idx[4]*8+c], q5 = g_h1h[idx[5]*8+c];
        uint4 q6 = g_h1h[idx[6]*8+c], q7 = g_h1h[idx[7]*8+c];
        ACCM(q0, m[0]) ACCM(q1, m[1]) ACCM(q2, m[2]) ACCM(q3, m[3])
        ACCM(q4, m[4]) ACCM(q5, m[5]) ACCM(q6, m[6]) ACCM(q7, m[7])
    }
    float dinv = g_dinv[n];
    uint4 o;
    o.x = ph2(a0*dinv, a1*dinv); o.y = ph2(a2*dinv, a3*dinv);
    o.z = ph2(a4*dinv, a5*dinv); o.w = ph2(a6*dinv, a7*dinv);
    g_ag2h[n*8 + c] = o;
}

// ---------------- dense updates: 2 nodes/thread, quarter-split, LDS.128 weights ------

__global__ void __launch_bounds__(256)
k_update1(const float* __restrict__ Wse, const float* __restrict__ Wne,
          const float* __restrict__ b) {
    __shared__ float sW[2 * EMB * HID];   // 16 KB
    __shared__ float sb[HID];
    int tid = threadIdx.x;
    for (int i = tid; i < EMB * HID; i += 256) { sW[i] = Wse[i]; sW[EMB*HID + i] = Wne[i]; }
    if (tid < HID) sb[tid] = b[tid];
    __syncthreads();

    int t = blockIdx.x * 256 + tid;
    if (t >= Nn / 2) return;          // Nn even: exactly 2 nodes per thread
    int n0 = t * 2, n1 = n0 + 1;

    #pragma unroll 1
    for (int q = 0; q < 4; q++) {     // quarter = 16 output cols
        u64 acc0[8], acc1[8];
        #pragma unroll
        for (int j2 = 0; j2 < 8; j2++) {
            u64 bi = pack2(sb[q*16 + 2*j2], sb[q*16 + 2*j2 + 1]);
            acc0[j2] = bi; acc1[j2] = bi;
        }
        #pragma unroll 1
        for (int kk = 0; kk < 4; kk++) {
            uint4 qh0 = g_h0h[n0*4 + kk], qa0 = g_ag1h[n0*4 + kk];
            uint4 qh1 = g_h0h[n1*4 + kk], qa1 = g_ag1h[n1*4 + kk];
            #pragma unroll
            for (int ch = 0; ch < 8; ch++) {
                int k = kk*8 + ch;
                const ulonglong2* ws = (const ulonglong2*)&sW[k * HID + q*16];
                const ulonglong2* wn = (const ulonglong2*)&sW[(EMB + k) * HID + q*16];
                float h0 = hget(qh0, ch), a0f = hget(qa0, ch);
                float h1 = hget(qh1, ch), a1f = hget(qa1, ch);
                u64 bh0 = pack2(h0, h0), ba0 = pack2(a0f, a0f);
                u64 bh1 = pack2(h1, h1), ba1 = pack2(a1f, a1f);
                #pragma unroll
                for (int j4 = 0; j4 < 4; j4++) {
                    ulonglong2 w = ws[j4], v = wn[j4];
                    fma2(acc0[j4*2+0], bh0, w.x); fma2(acc0[j4*2+1], bh0, w.y);
                    fma2(acc1[j4*2+0], bh1, w.x); fma2(acc1[j4*2+1], bh1, w.y);
                    fma2(acc0[j4*2+0], ba0, v.x); fma2(acc0[j4*2+1], ba0, v.y);
                    fma2(acc1[j4*2+0], ba1, v.x); fma2(acc1[j4*2+1], ba1, v.y);
                }
            }
        }
        #pragma unroll
        for (int half = 0; half < 2; half++) {
            float x0,x1,x2,x3,x4,x5,x6,x7;
            unpack2(x0,x1, acc0[half*4+0]); unpack2(x2,x3, acc0[half*4+1]);
            unpack2(x4,x5, acc0[half*4+2]); unpack2(x6,x7, acc0[half*4+3]);
            uint4 o;
            o.x = ph2(fmaxf(x0,0.f), fmaxf(x1,0.f));
            o.y = ph2(fmaxf(x2,0.f), fmaxf(x3,0.f));
            o.z = ph2(fmaxf(x4,0.f), fmaxf(x5,0.f));
            o.w = ph2(fmaxf(x6,0.f), fmaxf(x7,0.f));
            g_h1h[n0*8 + q*2 + half] = o;
            unpack2(x0,x1, acc1[half*4+0]); unpack2(x2,x3, acc1[half*4+1]);
            unpack2(x4,x5, acc1[half*4+2]); unpack2(x6,x7, acc1[half*4+3]);
            o.x = ph2(fmaxf(x0,0.f), fmaxf(x1,0.f));
            o.y = ph2(fmaxf(x2,0.f), fmaxf(x3,0.f));
            o.z = ph2(fmaxf(x4,0.f), fmaxf(x5,0.f));
            o.w = ph2(fmaxf(x6,0.f), fmaxf(x7,0.f));
            g_h1h[n1*8 + q*2 + half] = o;
        }
    }
}

__global__ void __launch_bounds__(256)
k_update2(const float* __restrict__ Wse, const float* __restrict__ Wne,
          const float* __restrict__ b, const int* __restrict__ graph_ids) {
    __shared__ float sW[2 * HID * HID];   // 32 KB
    __shared__ float sb[HID];
    int tid = threadIdx.x;
    for (int i = tid; i < HID * HID; i += 256) { sW[i] = Wse[i]; sW[HID*HID + i] = Wne[i]; }
    if (tid < HID) sb[tid] = b[tid];
    __syncthreads();

    int t = blockIdx.x * 256 + tid;
    if (t >= Nn / 2) return;
    int n0 = t * 2, n1 = n0 + 1;
    int g0 = graph_ids[n0], g1 = graph_ids[n1];
    float4* hg0 = (float4*)&g_hg[g0 * HID];
    float4* hg1 = (float4*)&g_hg[g1 * HID];

    #pragma unroll 1
    for (int q = 0; q < 4; q++) {
        u64 acc0[8], acc1[8];
        #pragma unroll
        for (int j2 = 0; j2 < 8; j2++) {
            u64 bi = pack2(sb[q*16 + 2*j2], sb[q*16 + 2*j2 + 1]);
            acc0[j2] = bi; acc1[j2] = bi;
        }
        #pragma unroll 1
        for (int kk = 0; kk < 8; kk++) {
            uint4 qh0 = g_h1h[n0*8 + kk], qa0 = g_ag2h[n0*8 + kk];
            uint4 qh1 = g_h1h[n1*8 + kk], qa1 = g_ag2h[n1*8 + kk];
            #pragma unroll
            for (int ch = 0; ch < 8; ch++) {
                int k = kk*8 + ch;
                const ulonglong2* ws = (const ulonglong2*)&sW[k * HID + q*16];
                const ulonglong2* wn = (const ulonglong2*)&sW[(HID + k) * HID + q*16];
                float h0 = hget(qh0, ch), a0f = hget(qa0, ch);
                float h1 = hget(qh1, ch), a1f = hget(qa1, ch);
                u64 bh0 = pack2(h0, h0), ba0 = pack2(a0f, a0f);
                u64 bh1 = pack2(h1, h1), ba1 = pack2(a1f, a1f);
                #pragma unroll
                for (int j4 = 0; j4 < 4; j4++) {
                    ulonglong2 w = ws[j4], v = wn[j4];
                    fma2(acc0[j4*2+0], bh0, w.x); fma2(acc0[j4*2+1], bh0, w.y);
                    fma2(acc1[j4*2+0], bh1, w.x); fma2(acc1[j4*2+1], bh1, w.y);
                    fma2(acc0[j4*2+0], ba0, v.x); fma2(acc0[j4*2+1], ba0, v.y);
                    fma2(acc1[j4*2+0], ba1, v.x); fma2(acc1[j4*2+1], ba1, v.y);
                }
            }
        }
        #pragma unroll
        for (int j4 = 0; j4 < 4; j4++) {
            float x0,x1,x2,x3;
            unpack2(x0, x1, acc0[j4*2+0]);
            unpack2(x2, x3, acc0[j4*2+1]);
            red4(&hg0[q*4 + j4], make_float4(fmaxf(x0,0.f), fmaxf(x1,0.f),
                                             fmaxf(x2,0.f), fmaxf(x3,0.f)));
            unpack2(x0, x1, acc1[j4*2+0]);
            unpack2(x2, x3, acc1[j4*2+1]);
            red4(&hg1[q*4 + j4], make_float4(fmaxf(x0,0.f), fmaxf(x1,0.f),
                                             fmaxf(x2,0.f), fmaxf(x3,0.f)));
        }
    }
}

// scorer
__global__ void k_final(const float* __restrict__ Ws1, const float* __restrict__ bs1,
                        const float* __restrict__ Ws2, const float* __restrict__ bs2,
                        float* __restrict__ out) {
    __shared__ float sW[HID * HID];
    int tid = threadIdx.x;
    for (int i = tid; i < HID * HID; i += 64) sW[i] = Ws1[i];
    __syncthreads();

    int g = blockIdx.x * 64 + tid;
    if (g >= Bb) return;

    float inv = 1.0f / fmaxf(g_cnt[g], 1.0f);
    float hv[HID];
    #pragma unroll
    for (int k = 0; k < HID; k++) hv[k] = g_hg[g * HID + k] * inv;

    float s = bs2[0];
    #pragma unroll 1
    for (int j = 0; j < HID; j++) {
        float t = bs1[j];
        #pragma unroll
        for (int k = 0; k < HID; k++) t += hv[k] * sW[k * HID + j];
        s += fmaxf(t, 0.f) * Ws2[j];
    }
    out[g] = s;
}

// ---------------- launcher ----------------
extern "C" void kernel_launch(void* const* d_in, const int* in_sizes, int n_in,
                              void* d_out, int out_size) {
    const int*    node_ids  = (const int*)   d_in[0];
    const int*    src       = (const int*)   d_in[1];
    const int*    dst       = (const int*)   d_in[2];
    const int*    graph_ids = (const int*)   d_in[3];
    const float4* emb       = (const float4*)d_in[4];
    const float*  W_self1   = (const float*) d_in[5];
    const float*  W_neigh1  = (const float*) d_in[6];
    const float*  b1        = (const float*) d_in[7];
    const float*  W_self2   = (const float*) d_in[8];
    const float*  W_neigh2  = (const float*) d_in[9];
    const float*  b2        = (const float*) d_in[10];
    const float*  Ws1       = (const float*) d_in[11];
    const float*  bs1       = (const float*) d_in[12];
    const float*  Ws2       = (const float*) d_in[13];
    const float*  bs2       = (const float*) d_in[14];
    float* out = (float*)d_out;

    k_zero       <<<512, 256>>>();
    k_deg        <<<(Ee + 255) / 256, 256>>>(dst, graph_ids);
    k_scan       <<<NT, 256>>>();
    k_fill_gather<<<(Ee + 255) / 256, 256>>>(src, dst, node_ids, emb);
    k_agg1       <<<(Nn * 4 + 255) / 256, 256>>>();
    k_update1    <<<(Nn/2 + 255) / 256, 256>>>(W_self1, W_neigh1, b1);
    k_agg2       <<<(Nn * 8 + 255) / 256, 256>>>();
    k_update2    <<<(Nn/2 + 255) / 256, 256>>>(W_self2, W_neigh2, b2, graph_ids);
    k_final      <<<(Bb + 63) / 64, 64>>>(Ws1, bs1, Ws2, bs2, out);
}